// round 4
// baseline (speedup 1.0000x reference)
#include <cuda_runtime.h>
#include <math.h>

#define NTOK   49
#define CDIM   256
#define HEADS  8
#define HD     32
#define BMAX   2048
#define NN2    2401   // 49*49

// Scratch (allocation-free: __device__ globals)
__device__ float g_qkv[BMAX * NTOK * 768];   // [M][768]  (q|k|v per row)
__device__ float g_att[BMAX * NTOK * CDIM];  // [M][256]
__device__ float g_bias[HEADS * NN2];        // 16*sigmoid(cpb)

__device__ __forceinline__ unsigned ldtf(const float* p) {
    unsigned u;
    asm("cvt.rna.tf32.f32 %0, %1;" : "=r"(u) : "f"(*p));
    return u;
}

__device__ __forceinline__ void mma_tf32(float* c, const unsigned* a, const unsigned* b) {
    asm volatile(
        "mma.sync.aligned.m16n8k8.row.col.f32.tf32.tf32.f32 "
        "{%0,%1,%2,%3}, {%4,%5,%6,%7}, {%8,%9}, {%0,%1,%2,%3};"
        : "+f"(c[0]), "+f"(c[1]), "+f"(c[2]), "+f"(c[3])
        : "r"(a[0]), "r"(a[1]), "r"(a[2]), "r"(a[3]), "r"(b[0]), "r"(b[1]));
}

#define CPA16(dst_u32, src_ptr) \
    asm volatile("cp.async.cg.shared.global [%0], [%1], 16;" :: "r"(dst_u32), "l"(src_ptr))

// ---------------------------------------------------------------------------
// CPB MLP (tiny, one block)
// ---------------------------------------------------------------------------
__global__ void cpb_kernel(const float* __restrict__ table,
                           const float* __restrict__ w1,
                           const float* __restrict__ b1,
                           const float* __restrict__ w2,
                           const int*   __restrict__ idx)
{
    __shared__ float t8[169][8];
    const int tid = threadIdx.x;
    for (int e = tid; e < 169 * 8; e += blockDim.x) {
        const int r = e >> 3, hh = e & 7;
        const float t0 = table[r * 2 + 0];
        const float t1 = table[r * 2 + 1];
        float s = 0.f;
        for (int j = 0; j < 512; ++j) {
            float hv = fmaf(t0, w1[j * 2 + 0], fmaf(t1, w1[j * 2 + 1], b1[j]));
            hv = fmaxf(hv, 0.f);
            s = fmaf(hv, w2[hh * 512 + j], s);
        }
        t8[r][hh] = s;
    }
    __syncthreads();
    for (int e = tid; e < HEADS * NN2; e += blockDim.x) {
        const int h = e / NN2, ij = e % NN2;
        const float bv = t8[idx[ij]][h];
        g_bias[e] = 16.f / (1.f + __expf(-bv));
    }
}

// ---------------------------------------------------------------------------
// 3-stage cp.async tf32 GEMM core. BM=128, BN=128, BK=16, 256 threads.
// One __syncthreads per K-chunk. Warp tile 64x32 (4x4 m16n8k8 frags).
// ---------------------------------------------------------------------------
#define GEMM_PIPE(XPTR, WPTR)                                                     \
    __shared__ float As[3][128][20];                                              \
    __shared__ float Bs[3][128][20];                                              \
    const int tid = threadIdx.x;                                                  \
    const int lane = tid & 31, wid = tid >> 5;                                    \
    const int g = lane >> 2, tg = lane & 3;                                       \
    const int wm = (wid & 1) * 64, wn = (wid >> 1) * 32;                          \
    const int m0 = blockIdx.y * 128, n0 = blockIdx.x * 128;                       \
    const int lrow = tid >> 2, lcol = (tid & 3) * 4;                              \
    const float* gA0 = (XPTR) + (size_t)(m0 + lrow) * 256 + lcol;                 \
    const float* gA1 = gA0 + (size_t)64 * 256;                                    \
    const float* gB0 = (WPTR) + (size_t)(n0 + lrow) * 256 + lcol;                 \
    const float* gB1 = gB0 + (size_t)64 * 256;                                    \
    const unsigned sA = (unsigned)__cvta_generic_to_shared(&As[0][lrow][lcol]);   \
    const unsigned sB = (unsigned)__cvta_generic_to_shared(&Bs[0][lrow][lcol]);   \
    const unsigned STG = 128 * 20 * 4;                                            \
    const unsigned HLF = 64 * 20 * 4;                                             \
    float acc[4][4][4];                                                           \
    _Pragma("unroll") for (int i = 0; i < 4; ++i)                                 \
    _Pragma("unroll") for (int j = 0; j < 4; ++j)                                 \
    _Pragma("unroll") for (int r = 0; r < 4; ++r) acc[i][j][r] = 0.f;             \
    _Pragma("unroll") for (int c = 0; c < 2; ++c) {                               \
        const unsigned so = c * STG;                                              \
        CPA16(sA + so,       gA0 + c * 16);                                       \
        CPA16(sA + so + HLF, gA1 + c * 16);                                       \
        CPA16(sB + so,       gB0 + c * 16);                                       \
        CPA16(sB + so + HLF, gB1 + c * 16);                                       \
        asm volatile("cp.async.commit_group;");                                   \
    }                                                                             \
    for (int kb = 0; kb < 16; ++kb) {                                             \
        if (kb < 15) asm volatile("cp.async.wait_group 1;");                      \
        else         asm volatile("cp.async.wait_group 0;");                      \
        __syncthreads();                                                          \
        if (kb + 2 < 16) {                                                        \
            const int c = kb + 2;                                                 \
            const unsigned so = (unsigned)(c % 3) * STG;                          \
            CPA16(sA + so,       gA0 + c * 16);                                   \
            CPA16(sA + so + HLF, gA1 + c * 16);                                   \
            CPA16(sB + so,       gB0 + c * 16);                                   \
            CPA16(sB + so + HLF, gB1 + c * 16);                                   \
            asm volatile("cp.async.commit_group;");                               \
        }                                                                         \
        const int s = kb % 3;                                                     \
        _Pragma("unroll") for (int ks = 0; ks < 2; ++ks) {                        \
            const int kk = ks * 8;                                                \
            unsigned af[4][4], bf[4][2];                                          \
            _Pragma("unroll") for (int mi = 0; mi < 4; ++mi) {                    \
                const int r = wm + mi * 16 + g;                                   \
                af[mi][0] = ldtf(&As[s][r    ][kk + tg]);                         \
                af[mi][1] = ldtf(&As[s][r + 8][kk + tg]);                         \
                af[mi][2] = ldtf(&As[s][r    ][kk + tg + 4]);                     \
                af[mi][3] = ldtf(&As[s][r + 8][kk + tg + 4]);                     \
            }                                                                     \
            _Pragma("unroll") for (int ni = 0; ni < 4; ++ni) {                    \
                const int c = wn + ni * 8 + g;                                    \
                bf[ni][0] = ldtf(&Bs[s][c][kk + tg]);                             \
                bf[ni][1] = ldtf(&Bs[s][c][kk + tg + 4]);                         \
            }                                                                     \
            _Pragma("unroll") for (int mi = 0; mi < 4; ++mi)                      \
            _Pragma("unroll") for (int ni = 0; ni < 4; ++ni)                      \
                mma_tf32(acc[mi][ni], af[mi], bf[ni]);                            \
        }                                                                         \
    }

// ---------------------------------------------------------------------------
// QKV GEMM: g_qkv[M,768] = X @ qkv_w^T + qkv_bias
// ---------------------------------------------------------------------------
__device__ __forceinline__ float qkvb(int o, const float* qb, const float* vb) {
    return (o < 256) ? qb[o] : ((o < 512) ? 0.f : vb[o - 512]);
}

__global__ __launch_bounds__(256) void mma_qkv(const float* __restrict__ X,
                                               const float* __restrict__ W,
                                               const float* __restrict__ qb,
                                               const float* __restrict__ vb)
{
    GEMM_PIPE(X, W)

#pragma unroll
    for (int mi = 0; mi < 4; ++mi) {
        const int mA = m0 + wm + mi * 16 + g;
#pragma unroll
        for (int ni = 0; ni < 4; ++ni) {
            const int o = n0 + wn + ni * 8 + tg * 2;
            const float b0 = qkvb(o, qb, vb), b1 = qkvb(o + 1, qb, vb);
            float2 v0 = make_float2(acc[mi][ni][0] + b0, acc[mi][ni][1] + b1);
            float2 v1 = make_float2(acc[mi][ni][2] + b0, acc[mi][ni][3] + b1);
            *(float2*)&g_qkv[(size_t)mA * 768 + o]       = v0;
            *(float2*)&g_qkv[(size_t)(mA + 8) * 768 + o] = v1;
        }
    }
}

// ---------------------------------------------------------------------------
// Proj GEMM: out[M,256] = g_att @ proj_w^T + proj_b
// ---------------------------------------------------------------------------
__global__ __launch_bounds__(256) void mma_proj(const float* __restrict__ W,
                                                const float* __restrict__ pb,
                                                float* __restrict__ out)
{
    GEMM_PIPE(g_att, W)

#pragma unroll
    for (int mi = 0; mi < 4; ++mi) {
        const int mA = m0 + wm + mi * 16 + g;
#pragma unroll
        for (int ni = 0; ni < 4; ++ni) {
            const int o = n0 + wn + ni * 8 + tg * 2;
            const float b0 = pb[o], b1 = pb[o + 1];
            float2 v0 = make_float2(acc[mi][ni][0] + b0, acc[mi][ni][1] + b1);
            float2 v1 = make_float2(acc[mi][ni][2] + b0, acc[mi][ni][3] + b1);
            *(float2*)&out[(size_t)mA * 256 + o]       = v0;
            *(float2*)&out[(size_t)(mA + 8) * 256 + o] = v1;
        }
    }
}

// ---------------------------------------------------------------------------
// Attention: one block per (b, h). 128 threads (4 warps).
// K and V cached in registers; shared reads are mostly broadcasts.
// ---------------------------------------------------------------------------
__global__ __launch_bounds__(128) void attn_kernel(const float* __restrict__ mask,
                                                   const float* __restrict__ logit_scale,
                                                   int nW)
{
    __shared__ float qn[NTOK][36];
    __shared__ float kn[NTOK][36];
    __shared__ float vt[32][52];     // transposed V: [d][token]
    __shared__ float at[NTOK][56];

    const int b = blockIdx.x, h = blockIdx.y;
    const int tid = threadIdx.x, w = tid >> 5, lane = tid & 31;
    const float scale = __expf(fminf(logit_scale[h], 4.605170185988092f)); // ln(100)

    const float* base = &g_qkv[(size_t)(b * NTOK) * 768 + h * HD];

    for (int r = w; r < NTOK; r += 4) {
        const float* rp = base + (size_t)r * 768;
        const float qv = rp[lane];
        const float kv = rp[256 + lane];
        const float vv = rp[512 + lane];
        float sq = qv * qv, sk = kv * kv;
#pragma unroll
        for (int o = 16; o > 0; o >>= 1) {
            sq += __shfl_xor_sync(0xffffffffu, sq, o);
            sk += __shfl_xor_sync(0xffffffffu, sk, o);
        }
        qn[r][lane] = qv * (scale / fmaxf(sqrtf(sq), 1e-12f));
        kn[r][lane] = kv / fmaxf(sqrtf(sk), 1e-12f);
        vt[lane][r] = vv;
    }
    __syncthreads();

    const int j2 = lane + 32;
    const int j2c = (j2 < NTOK) ? j2 : NTOK - 1;
    const float* bptr = &g_bias[h * NN2];
    const float* mptr = &mask[(size_t)(b % nW) * NN2];

    // cache two K token vectors per lane (dies after QK phase)
    float k0[32], k1[32];
#pragma unroll
    for (int d4 = 0; d4 < 8; ++d4) {
        const float4 a = *(const float4*)&kn[lane][d4 * 4];
        const float4 c = *(const float4*)&kn[j2c][d4 * 4];
        k0[d4 * 4 + 0] = a.x; k0[d4 * 4 + 1] = a.y; k0[d4 * 4 + 2] = a.z; k0[d4 * 4 + 3] = a.w;
        k1[d4 * 4 + 0] = c.x; k1[d4 * 4 + 1] = c.y; k1[d4 * 4 + 2] = c.z; k1[d4 * 4 + 3] = c.w;
    }

    // QK^T + bias + mask (q via smem broadcast, k in registers)
    for (int r = w; r < NTOK; r += 4) {
        float a0 = 0.f, a1 = 0.f;
#pragma unroll
        for (int d4 = 0; d4 < 8; ++d4) {
            const float4 q4 = *(const float4*)&qn[r][d4 * 4];
            a0 = fmaf(q4.x, k0[d4 * 4 + 0], a0); a1 = fmaf(q4.x, k1[d4 * 4 + 0], a1);
            a0 = fmaf(q4.y, k0[d4 * 4 + 1], a0); a1 = fmaf(q4.y, k1[d4 * 4 + 1], a1);
            a0 = fmaf(q4.z, k0[d4 * 4 + 2], a0); a1 = fmaf(q4.z, k1[d4 * 4 + 2], a1);
            a0 = fmaf(q4.w, k0[d4 * 4 + 3], a0); a1 = fmaf(q4.w, k1[d4 * 4 + 3], a1);
        }
        at[r][lane] = a0 + bptr[r * NTOK + lane] + mptr[r * NTOK + lane];
        if (j2 < NTOK) at[r][j2] = a1 + bptr[r * NTOK + j2] + mptr[r * NTOK + j2];
    }
    __syncthreads();

    // row softmax
    for (int r = w; r < NTOK; r += 4) {
        const float a0 = at[r][lane];
        const float a1 = (j2 < NTOK) ? at[r][j2] : -1e30f;
        float mx = fmaxf(a0, a1);
#pragma unroll
        for (int o = 16; o > 0; o >>= 1) mx = fmaxf(mx, __shfl_xor_sync(0xffffffffu, mx, o));
        const float e0 = __expf(a0 - mx);
        const float e1 = (j2 < NTOK) ? __expf(a1 - mx) : 0.f;
        float s = e0 + e1;
#pragma unroll
        for (int o = 16; o > 0; o >>= 1) s += __shfl_xor_sync(0xffffffffu, s, o);
        const float inv = 1.f / s;
        at[r][lane] = e0 * inv;
        if (j2 < NTOK) at[r][j2] = e1 * inv;
    }
    __syncthreads();

    // cache V slice per lane (lane == head dim)
    float vr[49];
#pragma unroll
    for (int j4 = 0; j4 < 12; ++j4) {
        const float4 v4 = *(const float4*)&vt[lane][j4 * 4];
        vr[j4 * 4 + 0] = v4.x; vr[j4 * 4 + 1] = v4.y;
        vr[j4 * 4 + 2] = v4.z; vr[j4 * 4 + 3] = v4.w;
    }
    vr[48] = vt[lane][48];

    // attn @ V (p via smem broadcast, v in registers)
    for (int r = w; r < NTOK; r += 4) {
        float acc = 0.f;
#pragma unroll
        for (int j4 = 0; j4 < 12; ++j4) {
            const float4 a4 = *(const float4*)&at[r][j4 * 4];
            acc = fmaf(a4.x, vr[j4 * 4 + 0], acc);
            acc = fmaf(a4.y, vr[j4 * 4 + 1], acc);
            acc = fmaf(a4.z, vr[j4 * 4 + 2], acc);
            acc = fmaf(a4.w, vr[j4 * 4 + 3], acc);
        }
        acc = fmaf(at[r][48], vr[48], acc);
        g_att[(size_t)(b * NTOK + r) * CDIM + h * HD + lane] = acc;
    }
}

// ---------------------------------------------------------------------------
extern "C" void kernel_launch(void* const* d_in, const int* in_sizes, int n_in,
                              void* d_out, int out_size)
{
    const float* x        = (const float*)d_in[0];
    const float* mask     = (const float*)d_in[1];
    const float* qkv_w    = (const float*)d_in[2];
    const float* q_bias   = (const float*)d_in[3];
    const float* v_bias   = (const float*)d_in[4];
    const float* logit_sc = (const float*)d_in[5];
    const float* cpb_w1   = (const float*)d_in[6];
    const float* cpb_b1   = (const float*)d_in[7];
    const float* cpb_w2   = (const float*)d_in[8];
    const float* proj_w   = (const float*)d_in[9];
    const float* proj_b   = (const float*)d_in[10];
    const float* table    = (const float*)d_in[11];
    const int*   rel_idx  = (const int*)d_in[12];

    const int B  = in_sizes[0] / (NTOK * CDIM);      // 2048
    const int nW = in_sizes[1] / NN2;                // 64
    const int M  = B * NTOK;                         // 100352

    mma_qkv<<<dim3(768 / 128, M / 128), 256>>>(x, qkv_w, q_bias, v_bias);
    cpb_kernel<<<1, 256>>>(table, cpb_w1, cpb_b1, cpb_w2, rel_idx);
    attn_kernel<<<dim3(B, HEADS), 128>>>(mask, logit_sc, nW);
    mma_proj<<<dim3(256 / 128, M / 128), 256>>>(proj_w, proj_b, (float*)d_out);
}